// round 13
// baseline (speedup 1.0000x reference)
#include <cuda_runtime.h>
#include <cuda_bf16.h>
#include <cstdint>

#define Bn 16
#define Nn 1024
#define Cc 64
#define Kk 5
#define KC 320      /* Kk*Cc */
#define Oo 64
#define Dd 10
#define WSZ 20480   /* KC*Oo */

#define ASTR 40     /* bf16 elems per A smem row (32+8 pad) -> 80 B   */
#define BSTR 72     /* bf16 elems per B smem row (64+8 pad) -> 144 B  */

// hop_mma dynamic smem layout (bytes), per ping-pong buffer:
#define AH_OFF 0
#define AL_OFF 10240
#define BH_OFF 20480
#define BL_OFF 25088
#define BUF_BYTES 29696
#define HOP_SMEM (2 * BUF_BYTES)   /* 59392 */

// Scratch (static device arrays — runtime allocation is forbidden).
__device__ float g_xg[(size_t)Bn * Nn * Kk * Cc];  // [b][n][k][c]
__device__ float g_W [(size_t)Nn * WSZ];           // [n][kc][o]

// ---- bf16 split helpers ----
// hi = truncate-to-bf16 (top 16 bits), lo = rn(f - hi). Error ~2^-17.
__device__ __forceinline__ uint32_t prmt_hi(uint32_t a, uint32_t b) {
    uint32_t d;
    asm("prmt.b32 %0, %1, %2, 0x7632;" : "=r"(d) : "r"(a), "r"(b));
    return d;
}
__device__ __forceinline__ uint32_t cvt_bf16x2(float lo, float hi) {
    uint32_t d;
    asm("cvt.rn.bf16x2.f32 %0, %1, %2;" : "=r"(d) : "f"(hi), "f"(lo));
    return d;
}
__device__ __forceinline__ void split2(float f0, float f1, uint32_t& h, uint32_t& l) {
    uint32_t b0 = __float_as_uint(f0), b1 = __float_as_uint(f1);
    h = prmt_hi(b0, b1);
    float r0 = f0 - __uint_as_float(b0 & 0xFFFF0000u);
    float r1 = f1 - __uint_as_float(b1 & 0xFFFF0000u);
    l = cvt_bf16x2(r0, r1);
}

__device__ __forceinline__ void mma16816(float* c, const uint32_t* a, const uint32_t* b) {
    asm volatile(
        "mma.sync.aligned.m16n8k16.row.col.f32.bf16.bf16.f32 "
        "{%0,%1,%2,%3}, {%4,%5,%6,%7}, {%8,%9}, {%0,%1,%2,%3};"
        : "+f"(c[0]), "+f"(c[1]), "+f"(c[2]), "+f"(c[3])
        : "r"(a[0]), "r"(a[1]), "r"(a[2]), "r"(a[3]), "r"(b[0]), "r"(b[1]));
}

__device__ __forceinline__ uint32_t smem_u32(const void* p) {
    uint32_t a;
    asm("{ .reg .u64 t; cvta.to.shared.u64 t, %1; cvt.u32.u64 %0, t; }"
        : "=r"(a) : "l"(p));
    return a;
}
__device__ __forceinline__ void ldsm_x4(uint32_t* r, uint32_t addr) {
    asm volatile("ldmatrix.sync.aligned.m8n8.x4.shared.b16 {%0,%1,%2,%3}, [%4];"
                 : "=r"(r[0]), "=r"(r[1]), "=r"(r[2]), "=r"(r[3]) : "r"(addr));
}
__device__ __forceinline__ void ldsm_x4_t(uint32_t* r, uint32_t addr) {
    asm volatile("ldmatrix.sync.aligned.m8n8.x4.trans.shared.b16 {%0,%1,%2,%3}, [%4];"
                 : "=r"(r[0]), "=r"(r[1]), "=r"(r[2]), "=r"(r[3]) : "r"(addr));
}
#define STS128(addr, r0, r1, r2, r3) \
    asm volatile("st.shared.v4.b32 [%0], {%1,%2,%3,%4};" \
                 :: "r"(addr), "r"(r0), "r"(r1), "r"(r2), "r"(r3) : "memory")
#define STS64(addr, r0, r1) \
    asm volatile("st.shared.v2.b32 [%0], {%1,%2};" \
                 :: "r"(addr), "r"(r0), "r"(r1) : "memory")

// ---------------------------------------------------------------------------
// Copy x into the k=0 slot of g_xg.
// ---------------------------------------------------------------------------
__global__ __launch_bounds__(256) void copy_x_kernel(const float* __restrict__ x) {
    int i = blockIdx.x * 256 + threadIdx.x;
    int bn = i >> 4;
    int c4 = (i & 15) << 2;
    float4 v = *(const float4*)(x + (size_t)bn * Cc + c4);
    *(float4*)(g_xg + (size_t)bn * KC + c4) = v;
}

// ---------------------------------------------------------------------------
// HMMA hop GEMM, double-buffered, 128 threads / 4 warps, warp tile 32x64.
// CTA 128(M) x 64(N), K=1024 in 32 chunks of 32; bf16 hi/lo split (3 terms).
// Warp-tile reshape removes A-side LDSM duplication (per-k16 LDSM 32->24 KB).
// ---------------------------------------------------------------------------
__global__ __launch_bounds__(128, 2) void hop_mma(const float* __restrict__ adj,
                                                  const float* __restrict__ x,
                                                  int kin_base, int kout_base) {
    extern __shared__ char dsm[];
    const uint32_t smb = smem_u32(dsm);

    const int s = blockIdx.z, b = blockIdx.y;
    const int row0 = blockIdx.x * 128;

    const float* A = adj + ((size_t)s * Bn + b) * Nn * Nn;
    const float* X;
    int ldx;
    if (kin_base < 0) { X = x    + (size_t)b * Nn * Cc;                         ldx = Cc; }
    else              { X = g_xg + (size_t)b * Nn * KC + (kin_base + 2*s) * Cc; ldx = KC; }
    float* Y = g_xg + (size_t)b * Nn * KC + (kout_base + 2*s) * Cc;

    const int tid = threadIdx.x, lane = tid & 31, wid = tid >> 5;  // wid 0..3
    const int g = lane >> 2, t = lane & 3;

    // --- gmem load mapping ---
    // A: one thread per row (128 rows), full 32-k chunk = 8 float4.
    const float* pAr = A + (size_t)(row0 + tid) * Nn;
    const uint32_t aoff = (uint32_t)(tid * (ASTR * 2));
    // B: bk = k-row (32), bc = col segment of 16 -> 4 float4.
    const int bk = tid >> 2, bc = (tid & 3) * 16;
    const float* pBr = X + (size_t)bk * ldx + bc;
    const uint32_t boff = (uint32_t)(bk * (BSTR * 2) + bc * 2);

    // --- LDSM fragment offsets (bytes, within region) ---
    const uint32_t rowA = (uint32_t)((wid * 32 + (lane & 15)) * (ASTR * 2) + (lane >> 4) * 16);
    const uint32_t rowB = (uint32_t)((lane & 15) * (BSTR * 2) + (lane >> 4) * 16);

    float acc[2][8][4];
#pragma unroll
    for (int mt = 0; mt < 2; ++mt)
#pragma unroll
        for (int nt = 0; nt < 8; ++nt)
#pragma unroll
            for (int i = 0; i < 4; ++i) acc[mt][nt][i] = 0.f;

    float4 fa[8], fb[4];
    // prefetch chunk 0
#pragma unroll
    for (int q = 0; q < 8; ++q) fa[q] = *(const float4*)(pAr + q * 4);
#pragma unroll
    for (int q = 0; q < 4; ++q) fb[q] = *(const float4*)(pBr + q * 4);

    // stage chunk 0 into buffer 0
    {
        uint32_t h[16], l[16];
#pragma unroll
        for (int q = 0; q < 8; ++q) {
            split2(fa[q].x, fa[q].y, h[2*q],     l[2*q]);
            split2(fa[q].z, fa[q].w, h[2*q + 1], l[2*q + 1]);
        }
#pragma unroll
        for (int q = 0; q < 4; ++q) {
            STS128(smb + AH_OFF + aoff + q * 16, h[4*q], h[4*q+1], h[4*q+2], h[4*q+3]);
            STS128(smb + AL_OFF + aoff + q * 16, l[4*q], l[4*q+1], l[4*q+2], l[4*q+3]);
        }
        uint32_t bh[8], bl[8];
#pragma unroll
        for (int q = 0; q < 4; ++q) {
            split2(fb[q].x, fb[q].y, bh[2*q],     bl[2*q]);
            split2(fb[q].z, fb[q].w, bh[2*q + 1], bl[2*q + 1]);
        }
        STS128(smb + BH_OFF + boff,      bh[0], bh[1], bh[2], bh[3]);
        STS128(smb + BH_OFF + boff + 16, bh[4], bh[5], bh[6], bh[7]);
        STS128(smb + BL_OFF + boff,      bl[0], bl[1], bl[2], bl[3]);
        STS128(smb + BL_OFF + boff + 16, bl[4], bl[5], bl[6], bl[7]);
    }
    __syncthreads();

#pragma unroll 1
    for (int kc = 0; kc < 32; ++kc) {
        const uint32_t cur = smb + (kc & 1) * BUF_BYTES;
        const uint32_t nxt = smb + ((kc + 1) & 1) * BUF_BYTES;

        // ---- issue next chunk's LDGs (overlap with MMA below) ----
        if (kc < 31) {
            const int k0 = (kc + 1) * 32;
#pragma unroll
            for (int q = 0; q < 8; ++q) fa[q] = *(const float4*)(pAr + k0 + q * 4);
#pragma unroll
            for (int q = 0; q < 4; ++q) fb[q] = *(const float4*)(pBr + (size_t)k0 * ldx + q * 4);
        }

        // ---- compute current chunk: two k16 sub-steps ----
#pragma unroll
        for (int ss = 0; ss < 2; ++ss) {
            const uint32_t ao = rowA + ss * 32;
            const uint32_t bo = rowB + (uint32_t)(ss * 16 * BSTR * 2);
            uint32_t ah[2][4], al[2][4];
            ldsm_x4(ah[0], cur + AH_OFF + ao);
            ldsm_x4(ah[1], cur + AH_OFF + ao + 16 * ASTR * 2);
            ldsm_x4(al[0], cur + AL_OFF + ao);
            ldsm_x4(al[1], cur + AL_OFF + ao + 16 * ASTR * 2);
#pragma unroll
            for (int p = 0; p < 4; ++p) {        // n-tile pairs: cols p*16
                uint32_t bh[4], bl[4];
                ldsm_x4_t(bh, cur + BH_OFF + bo + p * 32);
                ldsm_x4_t(bl, cur + BL_OFF + bo + p * 32);
#pragma unroll
                for (int mt = 0; mt < 2; ++mt)
#pragma unroll
                    for (int j = 0; j < 2; ++j) {
                        float* a4 = acc[mt][2*p + j];
                        mma16816(a4, ah[mt], &bh[2*j]);
                        mma16816(a4, ah[mt], &bl[2*j]);
                        mma16816(a4, al[mt], &bh[2*j]);
                    }
            }
        }

        // ---- stage next chunk into the idle buffer ----
        if (kc < 31) {
            uint32_t h[16], l[16];
#pragma unroll
            for (int q = 0; q < 8; ++q) {
                split2(fa[q].x, fa[q].y, h[2*q],     l[2*q]);
                split2(fa[q].z, fa[q].w, h[2*q + 1], l[2*q + 1]);
            }
#pragma unroll
            for (int q = 0; q < 4; ++q) {
                STS128(nxt + AH_OFF + aoff + q * 16, h[4*q], h[4*q+1], h[4*q+2], h[4*q+3]);
                STS128(nxt + AL_OFF + aoff + q * 16, l[4*q], l[4*q+1], l[4*q+2], l[4*q+3]);
            }
            uint32_t bh[8], bl[8];
#pragma unroll
            for (int q = 0; q < 4; ++q) {
                split2(fb[q].x, fb[q].y, bh[2*q],     bl[2*q]);
                split2(fb[q].z, fb[q].w, bh[2*q + 1], bl[2*q + 1]);
            }
            STS128(nxt + BH_OFF + boff,      bh[0], bh[1], bh[2], bh[3]);
            STS128(nxt + BH_OFF + boff + 16, bh[4], bh[5], bh[6], bh[7]);
            STS128(nxt + BL_OFF + boff,      bl[0], bl[1], bl[2], bl[3]);
            STS128(nxt + BL_OFF + boff + 16, bl[4], bl[5], bl[6], bl[7]);
        }
        __syncthreads();
    }

    // ---- epilogue: warp wid owns rows wid*32..+31, all 64 cols ----
#pragma unroll
    for (int mt = 0; mt < 2; ++mt) {
        const int rA = row0 + wid * 32 + mt * 16 + g;
#pragma unroll
        for (int nt = 0; nt < 8; ++nt) {
            const int col = nt * 8 + t * 2;
            *(float2*)(Y + (size_t)rA * KC + col) =
                make_float2(acc[mt][nt][0], acc[mt][nt][1]);
            *(float2*)(Y + (size_t)(rA + 8) * KC + col) =
                make_float2(acc[mt][nt][2], acc[mt][nt][3]);
        }
    }
}

// ---------------------------------------------------------------------------
// W[n, j] = sum_d emb[n,d] * wp[d, j]. grid (320, 4).
// ---------------------------------------------------------------------------
#define JC 64
__global__ __launch_bounds__(256) void make_weights(const float* __restrict__ emb,
                                                    const float* __restrict__ wp) {
    __shared__ float wpS[Dd][JC];
    __shared__ float eS[256][Dd];
    const int j0  = blockIdx.x * JC;
    const int n0  = blockIdx.y * 256;
    const int tid = threadIdx.x;

    for (int p = tid; p < Dd * JC; p += 256)
        wpS[p / JC][p % JC] = wp[(size_t)(p / JC) * WSZ + j0 + (p % JC)];
    for (int p = tid; p < 256 * Dd; p += 256)
        eS[p / Dd][p % Dd] = emb[(size_t)(n0 + p / Dd) * Dd + (p % Dd)];
    __syncthreads();

    const int jj = tid & 63;
    const int tl = tid >> 6;
    for (int i = 0; i < 64; ++i) {
        int nl = i * 4 + tl;
        float s = 0.f;
#pragma unroll
        for (int d = 0; d < Dd; ++d) s += eS[nl][d] * wpS[d][jj];
        g_W[(size_t)(n0 + nl) * WSZ + j0 + jj] = s;
    }
}

// ---------------------------------------------------------------------------
// final_contract via HMMA: per node n, out[., n, .] = Xn[16 x 320] @ Wn[320 x 64]
// + bias. Xn staged once as bf16 hi/lo; W streamed in k16 chunks
// (double-buffered), bf16 hi/lo; 3-term split. Warp w owns n8 tile at cols 8w.
// ---------------------------------------------------------------------------
#define XSTR 328   /* bf16 elems per Xs row -> 656 B */
__global__ __launch_bounds__(256) void final_contract(const float* __restrict__ emb,
                                                      const float* __restrict__ bias_pool,
                                                      float* __restrict__ out) {
    __shared__ uint16_t XsH[Bn * XSTR], XsL[Bn * XSTR];      // 10496 B each
    __shared__ uint16_t WsH[2][16 * BSTR], WsL[2][16 * BSTR];// 2304 B each buf

    const int n   = blockIdx.x;
    const int tid = threadIdx.x, lane = tid & 31, wid = tid >> 5;
    const int g = lane >> 2, t = lane & 3;

    const uint32_t XsHb = smem_u32(XsH), XsLb = smem_u32(XsL);
    const uint32_t WsHb = smem_u32(WsH), WsLb = smem_u32(WsL);
    const float* Wn = g_W + (size_t)n * WSZ;

    // ---- stage Xn (16 x 320 fp32 -> bf16 hi/lo) ----
    for (int p = tid; p < Bn * KC / 4; p += 256) {
        int b = p / 80, c4 = (p % 80) << 2;
        float4 v = *(const float4*)(g_xg + ((size_t)b * Nn + n) * KC + c4);
        uint32_t h0, l0, h1, l1;
        split2(v.x, v.y, h0, l0);
        split2(v.z, v.w, h1, l1);
        uint32_t off = (uint32_t)(b * XSTR + c4) * 2;
        STS64(XsHb + off, h0, h1);
        STS64(XsLb + off, l0, l1);
    }

    // ---- stage W chunk 0 ----
    {
        int r = tid >> 4, c4 = (tid & 15) << 2;
        float4 v = *(const float4*)(Wn + (size_t)r * Oo + c4);
        uint32_t h0, l0, h1, l1;
        split2(v.x, v.y, h0, l0);
        split2(v.z, v.w, h1, l1);
        uint32_t off = (uint32_t)(r * BSTR + c4) * 2;
        STS64(WsHb + off, h0, h1);
        STS64(WsLb + off, l0, l1);
    }
    __syncthreads();

    // LDSM offsets
    const uint32_t xfrag = (uint32_t)((lane & 15) * XSTR + (lane >> 4) * 8) * 2;
    const uint32_t wfrag = (uint32_t)((lane & 15) * BSTR + (lane >> 4) * 8 + (wid >> 1) * 16) * 2;
    const int nsel = wid & 1;
    const uint32_t wbufB = (uint32_t)(16 * BSTR * 2);

    float acc[4] = {0.f, 0.f, 0.f, 0.f};
    float4 wv;
    const int wr = tid >> 4, wc4 = (tid & 15) << 2;
    const uint32_t woff = (uint32_t)(wr * BSTR + wc4) * 2;

#pragma unroll 1
    for (int kc = 0; kc < 20; ++kc) {
        const uint32_t cur = (kc & 1) * wbufB;
        const uint32_t nxt = ((kc + 1) & 1) * wbufB;

        if (kc < 19)
            wv = *(const float4*)(Wn + (size_t)((kc + 1) * 16 + wr) * Oo + wc4);

        uint32_t xh[4], xl[4], wh[4], wl[4];
        ldsm_x4  (xh, XsHb + xfrag + kc * 32);
        ldsm_x4  (xl, XsLb + xfrag + kc * 32);
        ldsm_x4_t(wh, WsHb + cur + wfrag);
        ldsm_x4_t(wl, WsLb + cur + wfrag);
        const uint32_t bh2[2] = { wh[2 * nsel], wh[2 * nsel + 1] };
        const uint32_t bl2[2] = { wl[2 * nsel], wl[2 * nsel + 1] };
        mma16816(acc, xh, bh2);
        mma16816(acc, xh, bl2);
        mma16816(acc, xl, bh2);

        if (kc < 19) {
            uint32_t h0, l0, h1, l1;
            split2(wv.x, wv.y, h0, l0);
            split2(wv.z, wv.w, h1, l1);
            STS64(WsHb + nxt + woff, h0, h1);
            STS64(WsLb + nxt + woff, l0, l1);
        }
        __syncthreads();
    }

    // ---- epilogue: rows g, g+8 (batch), cols 8*wid + t*2 ----
    const int o = wid * 8 + t * 2;
    float b0 = 0.f, b1 = 0.f;
#pragma unroll
    for (int d = 0; d < Dd; ++d) {
        float e = emb[n * Dd + d];
        b0 += e * bias_pool[d * Oo + o];
        b1 += e * bias_pool[d * Oo + o + 1];
    }
    *(float2*)(out + ((size_t)g * Nn + n) * Oo + o) =
        make_float2(acc[0] + b0, acc[1] + b1);
    *(float2*)(out + ((size_t)(g + 8) * Nn + n) * Oo + o) =
        make_float2(acc[2] + b0, acc[3] + b1);
}

// ---------------------------------------------------------------------------
extern "C" void kernel_launch(void* const* d_in, const int* in_sizes, int n_in,
                              void* d_out, int out_size) {
    const float* x         = (const float*)d_in[0];  // [16,1024,64]
    const float* adj       = (const float*)d_in[1];  // [2,16,1024,1024]
    const float* emb       = (const float*)d_in[2];  // [1024,10]
    const float* wp        = (const float*)d_in[3];  // [10,5,64,64]
    const float* bias_pool = (const float*)d_in[4];  // [10,64]
    float*       out       = (float*)d_out;          // [16,1024,64]

    static int attr_set = 0;
    if (!attr_set) {
        cudaFuncSetAttribute(hop_mma, cudaFuncAttributeMaxDynamicSharedMemorySize,
                             HOP_SMEM);
        attr_set = 1;
    }

    copy_x_kernel<<<1024, 256>>>(x);
    make_weights <<<dim3(WSZ / JC, 4), 256>>>(emb, wp);

    dim3 g(Nn / 128, Bn, 2);
    hop_mma<<<g, 128, HOP_SMEM>>>(adj, x, -1, 1);   // stage 1: x -> slice 1+2s
    hop_mma<<<g, 128, HOP_SMEM>>>(adj, x,  1, 2);   // stage 2: slice 1+2s -> 2+2s

    final_contract<<<1024, 256>>>(emb, bias_pool, out);
}

// round 14
// speedup vs baseline: 1.2094x; 1.2094x over previous
#include <cuda_runtime.h>
#include <cuda_bf16.h>
#include <cstdint>

#define Bn 16
#define Nn 1024
#define Cc 64
#define Kk 5
#define KC 320      /* Kk*Cc */
#define Oo 64
#define Dd 10
#define WSZ 20480   /* KC*Oo */

#define ASTR 40     /* bf16 elems per A smem row (32+8 pad) -> 80 B   */
#define BSTR 72     /* bf16 elems per B smem row (64+8 pad) -> 144 B  */

// hop_mma dynamic smem layout (bytes), per ping-pong buffer:
#define AH_OFF 0
#define AL_OFF 10240
#define BH_OFF 20480
#define BL_OFF 25088
#define BUF_BYTES 29696
#define HOP_SMEM (2 * BUF_BYTES)   /* 59392 */

// Scratch (static device arrays — runtime allocation is forbidden).
// g_xg slice 0 is unused (final_contract reads x directly); slices 1..4 hold hops.
__device__ float g_xg[(size_t)Bn * Nn * Kk * Cc];  // [b][n][k][c]
__device__ float g_W [(size_t)Nn * WSZ];           // [n][kc][o]

// ---- bf16 split helpers ----
// hi = truncate-to-bf16 (top 16 bits), lo = rn(f - hi). Error ~2^-17.
__device__ __forceinline__ uint32_t prmt_hi(uint32_t a, uint32_t b) {
    uint32_t d;
    asm("prmt.b32 %0, %1, %2, 0x7632;" : "=r"(d) : "r"(a), "r"(b));
    return d;
}
__device__ __forceinline__ uint32_t cvt_bf16x2(float lo, float hi) {
    uint32_t d;
    asm("cvt.rn.bf16x2.f32 %0, %1, %2;" : "=r"(d) : "f"(hi), "f"(lo));
    return d;
}
__device__ __forceinline__ void split2(float f0, float f1, uint32_t& h, uint32_t& l) {
    uint32_t b0 = __float_as_uint(f0), b1 = __float_as_uint(f1);
    h = prmt_hi(b0, b1);
    float r0 = f0 - __uint_as_float(b0 & 0xFFFF0000u);
    float r1 = f1 - __uint_as_float(b1 & 0xFFFF0000u);
    l = cvt_bf16x2(r0, r1);
}

__device__ __forceinline__ void mma16816(float* c, const uint32_t* a, const uint32_t* b) {
    asm volatile(
        "mma.sync.aligned.m16n8k16.row.col.f32.bf16.bf16.f32 "
        "{%0,%1,%2,%3}, {%4,%5,%6,%7}, {%8,%9}, {%0,%1,%2,%3};"
        : "+f"(c[0]), "+f"(c[1]), "+f"(c[2]), "+f"(c[3])
        : "r"(a[0]), "r"(a[1]), "r"(a[2]), "r"(a[3]), "r"(b[0]), "r"(b[1]));
}

__device__ __forceinline__ uint32_t smem_u32(const void* p) {
    uint32_t a;
    asm("{ .reg .u64 t; cvta.to.shared.u64 t, %1; cvt.u32.u64 %0, t; }"
        : "=r"(a) : "l"(p));
    return a;
}
__device__ __forceinline__ void ldsm_x4(uint32_t* r, uint32_t addr) {
    asm volatile("ldmatrix.sync.aligned.m8n8.x4.shared.b16 {%0,%1,%2,%3}, [%4];"
                 : "=r"(r[0]), "=r"(r[1]), "=r"(r[2]), "=r"(r[3]) : "r"(addr));
}
__device__ __forceinline__ void ldsm_x4_t(uint32_t* r, uint32_t addr) {
    asm volatile("ldmatrix.sync.aligned.m8n8.x4.trans.shared.b16 {%0,%1,%2,%3}, [%4];"
                 : "=r"(r[0]), "=r"(r[1]), "=r"(r[2]), "=r"(r[3]) : "r"(addr));
}
#define STS128(addr, r0, r1, r2, r3) \
    asm volatile("st.shared.v4.b32 [%0], {%1,%2,%3,%4};" \
                 :: "r"(addr), "r"(r0), "r"(r1), "r"(r2), "r"(r3) : "memory")
#define STS64(addr, r0, r1) \
    asm volatile("st.shared.v2.b32 [%0], {%1,%2};" \
                 :: "r"(addr), "r"(r0), "r"(r1) : "memory")

// ---------------------------------------------------------------------------
// HMMA hop GEMM (R11 winning config): 256 threads / 8 warps, warp grid 4Mx2N,
// warp tile 32x32, double-buffered smem, bf16 hi/lo split (3 terms).
// CTA 128(M) x 64(N), K=1024 in 32 chunks of 32.
// ---------------------------------------------------------------------------
__global__ __launch_bounds__(256, 2) void hop_mma(const float* __restrict__ adj,
                                                  const float* __restrict__ x,
                                                  int kin_base, int kout_base) {
    extern __shared__ char dsm[];
    const uint32_t smb = smem_u32(dsm);

    const int s = blockIdx.z, b = blockIdx.y;
    const int row0 = blockIdx.x * 128;

    const float* A = adj + ((size_t)s * Bn + b) * Nn * Nn;
    const float* X;
    int ldx;
    if (kin_base < 0) { X = x    + (size_t)b * Nn * Cc;                         ldx = Cc; }
    else              { X = g_xg + (size_t)b * Nn * KC + (kin_base + 2*s) * Cc; ldx = KC; }
    float* Y = g_xg + (size_t)b * Nn * KC + (kout_base + 2*s) * Cc;

    const int tid = threadIdx.x, lane = tid & 31, wid = tid >> 5;
    const int g = lane >> 2, t = lane & 3;
    const int warpM = wid & 3, warpN = wid >> 2;

    // --- gmem load mapping ---
    const int ar = tid >> 1, aks = (tid & 1) * 16;        // A: row, k-half
    const float* pAr = A + (size_t)(row0 + ar) * Nn + aks;
    const uint32_t aoff = (uint32_t)(ar * (ASTR * 2) + aks * 2);
    const int bk = tid >> 3, bc = (tid & 7) * 8;          // B: k-row, col-seg
    const float* pBr = X + (size_t)bk * ldx + bc;
    const uint32_t boff = (uint32_t)(bk * (BSTR * 2) + bc * 2);

    // --- LDSM fragment offsets (bytes, within region) ---
    const uint32_t rowA = (uint32_t)((warpM * 32 + (lane & 15)) * (ASTR * 2) + (lane >> 4) * 16);
    const uint32_t rowB = (uint32_t)((lane & 15) * (BSTR * 2) + (lane >> 4) * 16 + warpN * 64);

    float acc[2][4][4];
#pragma unroll
    for (int mt = 0; mt < 2; ++mt)
#pragma unroll
        for (int nt = 0; nt < 4; ++nt)
#pragma unroll
            for (int i = 0; i < 4; ++i) acc[mt][nt][i] = 0.f;

    float4 fa[4], fb[2];
    // prefetch chunk 0
#pragma unroll
    for (int q = 0; q < 4; ++q) fa[q] = *(const float4*)(pAr + q * 4);
    fb[0] = *(const float4*)(pBr);
    fb[1] = *(const float4*)(pBr + 4);

    // stage chunk 0 into buffer 0
    {
        uint32_t h[8], l[8];
#pragma unroll
        for (int q = 0; q < 4; ++q) {
            split2(fa[q].x, fa[q].y, h[2*q],     l[2*q]);
            split2(fa[q].z, fa[q].w, h[2*q + 1], l[2*q + 1]);
        }
        STS128(smb + AH_OFF + aoff,      h[0], h[1], h[2], h[3]);
        STS128(smb + AH_OFF + aoff + 16, h[4], h[5], h[6], h[7]);
        STS128(smb + AL_OFF + aoff,      l[0], l[1], l[2], l[3]);
        STS128(smb + AL_OFF + aoff + 16, l[4], l[5], l[6], l[7]);
        uint32_t bh[4], bl[4];
        split2(fb[0].x, fb[0].y, bh[0], bl[0]);
        split2(fb[0].z, fb[0].w, bh[1], bl[1]);
        split2(fb[1].x, fb[1].y, bh[2], bl[2]);
        split2(fb[1].z, fb[1].w, bh[3], bl[3]);
        STS128(smb + BH_OFF + boff, bh[0], bh[1], bh[2], bh[3]);
        STS128(smb + BL_OFF + boff, bl[0], bl[1], bl[2], bl[3]);
    }
    __syncthreads();

#pragma unroll 1
    for (int kc = 0; kc < 32; ++kc) {
        const uint32_t cur = smb + (kc & 1) * BUF_BYTES;
        const uint32_t nxt = smb + ((kc + 1) & 1) * BUF_BYTES;

        // ---- issue next chunk's LDGs (overlap with MMA below) ----
        if (kc < 31) {
            const int k0 = (kc + 1) * 32;
#pragma unroll
            for (int q = 0; q < 4; ++q) fa[q] = *(const float4*)(pAr + k0 + q * 4);
            fb[0] = *(const float4*)(pBr + (size_t)k0 * ldx);
            fb[1] = *(const float4*)(pBr + (size_t)k0 * ldx + 4);
        }

        // ---- compute current chunk: two k16 sub-steps ----
#pragma unroll
        for (int ss = 0; ss < 2; ++ss) {
            const uint32_t ao = rowA + ss * 32;
            const uint32_t bo = rowB + (uint32_t)(ss * 16 * BSTR * 2);
            uint32_t ah[2][4], al[2][4], bhf[2][4], blf[2][4];
            ldsm_x4  (ah[0], cur + AH_OFF + ao);
            ldsm_x4  (ah[1], cur + AH_OFF + ao + 16 * ASTR * 2);
            ldsm_x4  (al[0], cur + AL_OFF + ao);
            ldsm_x4  (al[1], cur + AL_OFF + ao + 16 * ASTR * 2);
            ldsm_x4_t(bhf[0], cur + BH_OFF + bo);
            ldsm_x4_t(bhf[1], cur + BH_OFF + bo + 32);
            ldsm_x4_t(blf[0], cur + BL_OFF + bo);
            ldsm_x4_t(blf[1], cur + BL_OFF + bo + 32);

#pragma unroll
            for (int mt = 0; mt < 2; ++mt)
#pragma unroll
                for (int nt = 0; nt < 4; ++nt) {
                    const uint32_t* bh2 = &bhf[nt >> 1][(nt & 1) * 2];
                    const uint32_t* bl2 = &blf[nt >> 1][(nt & 1) * 2];
                    mma16816(acc[mt][nt], ah[mt], bh2);
                    mma16816(acc[mt][nt], ah[mt], bl2);
                    mma16816(acc[mt][nt], al[mt], bh2);
                }
        }

        // ---- stage next chunk into the idle buffer ----
        if (kc < 31) {
            uint32_t h[8], l[8];
#pragma unroll
            for (int q = 0; q < 4; ++q) {
                split2(fa[q].x, fa[q].y, h[2*q],     l[2*q]);
                split2(fa[q].z, fa[q].w, h[2*q + 1], l[2*q + 1]);
            }
            STS128(nxt + AH_OFF + aoff,      h[0], h[1], h[2], h[3]);
            STS128(nxt + AH_OFF + aoff + 16, h[4], h[5], h[6], h[7]);
            STS128(nxt + AL_OFF + aoff,      l[0], l[1], l[2], l[3]);
            STS128(nxt + AL_OFF + aoff + 16, l[4], l[5], l[6], l[7]);
            uint32_t bh[4], bl[4];
            split2(fb[0].x, fb[0].y, bh[0], bl[0]);
            split2(fb[0].z, fb[0].w, bh[1], bl[1]);
            split2(fb[1].x, fb[1].y, bh[2], bl[2]);
            split2(fb[1].z, fb[1].w, bh[3], bl[3]);
            STS128(nxt + BH_OFF + boff, bh[0], bh[1], bh[2], bh[3]);
            STS128(nxt + BL_OFF + boff, bl[0], bl[1], bl[2], bl[3]);
        }
        __syncthreads();
    }

    // ---- epilogue ----
#pragma unroll
    for (int mt = 0; mt < 2; ++mt) {
        const int rA = row0 + warpM * 32 + mt * 16 + g;
#pragma unroll
        for (int nt = 0; nt < 4; ++nt) {
            const int col = warpN * 32 + nt * 8 + t * 2;
            *(float2*)(Y + (size_t)rA * KC + col) =
                make_float2(acc[mt][nt][0], acc[mt][nt][1]);
            *(float2*)(Y + (size_t)(rA + 8) * KC + col) =
                make_float2(acc[mt][nt][2], acc[mt][nt][3]);
        }
    }
}

// ---------------------------------------------------------------------------
// W[n, j] = sum_d emb[n,d] * wp[d, j]. grid (320, 4).
// ---------------------------------------------------------------------------
#define JC 64
__global__ __launch_bounds__(256) void make_weights(const float* __restrict__ emb,
                                                    const float* __restrict__ wp) {
    __shared__ float wpS[Dd][JC];
    __shared__ float eS[256][Dd];
    const int j0  = blockIdx.x * JC;
    const int n0  = blockIdx.y * 256;
    const int tid = threadIdx.x;

    for (int p = tid; p < Dd * JC; p += 256)
        wpS[p / JC][p % JC] = wp[(size_t)(p / JC) * WSZ + j0 + (p % JC)];
    for (int p = tid; p < 256 * Dd; p += 256)
        eS[p / Dd][p % Dd] = emb[(size_t)(n0 + p / Dd) * Dd + (p % Dd)];
    __syncthreads();

    const int jj = tid & 63;
    const int tl = tid >> 6;
    for (int i = 0; i < 64; ++i) {
        int nl = i * 4 + tl;
        float s = 0.f;
#pragma unroll
        for (int d = 0; d < Dd; ++d) s += eS[nl][d] * wpS[d][jj];
        g_W[(size_t)(n0 + nl) * WSZ + j0 + jj] = s;
    }
}

// ---------------------------------------------------------------------------
// final_contract via HMMA: per node n, out[., n, .] = Xn[16 x 320] @ Wn[320 x 64]
// + bias. Slice 0 of Xn comes straight from the input x (g_xg slice 0 unused);
// slices 1..4 from g_xg. Xn staged once as bf16 hi/lo; W streamed in k16
// chunks (double-buffered), bf16 hi/lo; 3-term split.
// ---------------------------------------------------------------------------
#define XSTR 328   /* bf16 elems per Xs row -> 656 B */
__global__ __launch_bounds__(256) void final_contract(const float* __restrict__ x,
                                                      const float* __restrict__ emb,
                                                      const float* __restrict__ bias_pool,
                                                      float* __restrict__ out) {
    __shared__ uint16_t XsH[Bn * XSTR], XsL[Bn * XSTR];      // 10496 B each
    __shared__ uint16_t WsH[2][16 * BSTR], WsL[2][16 * BSTR];// 2304 B each buf

    const int n   = blockIdx.x;
    const int tid = threadIdx.x, lane = tid & 31, wid = tid >> 5;
    const int g = lane >> 2, t = lane & 3;

    const uint32_t XsHb = smem_u32(XsH), XsLb = smem_u32(XsL);
    const uint32_t WsHb = smem_u32(WsH), WsLb = smem_u32(WsL);
    const float* Wn = g_W + (size_t)n * WSZ;

    // ---- stage Xn (16 x 320 fp32 -> bf16 hi/lo); col<64 from x, rest g_xg ----
    for (int p = tid; p < Bn * KC / 4; p += 256) {
        int b = p / 80, c4 = (p % 80) << 2;
        const float* src = (c4 < Cc)
            ? (x    + ((size_t)b * Nn + n) * Cc + c4)
            : (g_xg + ((size_t)b * Nn + n) * KC + c4);
        float4 v = *(const float4*)src;
        uint32_t h0, l0, h1, l1;
        split2(v.x, v.y, h0, l0);
        split2(v.z, v.w, h1, l1);
        uint32_t off = (uint32_t)(b * XSTR + c4) * 2;
        STS64(XsHb + off, h0, h1);
        STS64(XsLb + off, l0, l1);
    }

    // ---- stage W chunk 0 ----
    {
        int r = tid >> 4, c4 = (tid & 15) << 2;
        float4 v = *(const float4*)(Wn + (size_t)r * Oo + c4);
        uint32_t h0, l0, h1, l1;
        split2(v.x, v.y, h0, l0);
        split2(v.z, v.w, h1, l1);
        uint32_t off = (uint32_t)(r * BSTR + c4) * 2;
        STS64(WsHb + off, h0, h1);
        STS64(WsLb + off, l0, l1);
    }
    __syncthreads();

    // LDSM offsets
    const uint32_t xfrag = (uint32_t)((lane & 15) * XSTR + (lane >> 4) * 8) * 2;
    const uint32_t wfrag = (uint32_t)((lane & 15) * BSTR + (lane >> 4) * 8 + (wid >> 1) * 16) * 2;
    const int nsel = wid & 1;
    const uint32_t wbufB = (uint32_t)(16 * BSTR * 2);

    float acc[4] = {0.f, 0.f, 0.f, 0.f};
    float4 wv;
    const int wr = tid >> 4, wc4 = (tid & 15) << 2;
    const uint32_t woff = (uint32_t)(wr * BSTR + wc4) * 2;

#pragma unroll 1
    for (int kc = 0; kc < 20; ++kc) {
        const uint32_t cur = (kc & 1) * wbufB;
        const uint32_t nxt = ((kc + 1) & 1) * wbufB;

        if (kc < 19)
            wv = *(const float4*)(Wn + (size_t)((kc + 1) * 16 + wr) * Oo + wc4);

        uint32_t xh[4], xl[4], wh[4], wl[4];
        ldsm_x4  (xh, XsHb + xfrag + kc * 32);
        ldsm_x4  (xl, XsLb + xfrag + kc * 32);
        ldsm_x4_t(wh, WsHb + cur + wfrag);
        ldsm_x4_t(wl, WsLb + cur + wfrag);
        const uint32_t bh2[2] = { wh[2 * nsel], wh[2 * nsel + 1] };
        const uint32_t bl2[2] = { wl[2 * nsel], wl[2 * nsel + 1] };
        mma16816(acc, xh, bh2);
        mma16816(acc, xh, bl2);
        mma16816(acc, xl, bh2);

        if (kc < 19) {
            uint32_t h0, l0, h1, l1;
            split2(wv.x, wv.y, h0, l0);
            split2(wv.z, wv.w, h1, l1);
            STS64(WsHb + nxt + woff, h0, h1);
            STS64(WsLb + nxt + woff, l0, l1);
        }
        __syncthreads();
    }

    // ---- epilogue: rows g, g+8 (batch), cols 8*wid + t*2 ----
    const int o = wid * 8 + t * 2;
    float b0 = 0.f, b1 = 0.f;
#pragma unroll
    for (int d = 0; d < Dd; ++d) {
        float e = emb[n * Dd + d];
        b0 += e * bias_pool[d * Oo + o];
        b1 += e * bias_pool[d * Oo + o + 1];
    }
    *(float2*)(out + ((size_t)g * Nn + n) * Oo + o) =
        make_float2(acc[0] + b0, acc[1] + b1);
    *(float2*)(out + ((size_t)(g + 8) * Nn + n) * Oo + o) =
        make_float2(acc[2] + b0, acc[3] + b1);
}

// ---------------------------------------------------------------------------
extern "C" void kernel_launch(void* const* d_in, const int* in_sizes, int n_in,
                              void* d_out, int out_size) {
    const float* x         = (const float*)d_in[0];  // [16,1024,64]
    const float* adj       = (const float*)d_in[1];  // [2,16,1024,1024]
    const float* emb       = (const float*)d_in[2];  // [1024,10]
    const float* wp        = (const float*)d_in[3];  // [10,5,64,64]
    const float* bias_pool = (const float*)d_in[4];  // [10,64]
    float*       out       = (float*)d_out;          // [16,1024,64]

    static int attr_set = 0;
    if (!attr_set) {
        cudaFuncSetAttribute(hop_mma, cudaFuncAttributeMaxDynamicSharedMemorySize,
                             HOP_SMEM);
        attr_set = 1;
    }

    make_weights<<<dim3(WSZ / JC, 4), 256>>>(emb, wp);

    dim3 g(Nn / 128, Bn, 2);
    hop_mma<<<g, 256, HOP_SMEM>>>(adj, x, -1, 1);   // stage 1: x -> slice 1+2s
    hop_mma<<<g, 256, HOP_SMEM>>>(adj, x,  1, 2);   // stage 2: slice 1+2s -> 2+2s

    final_contract<<<1024, 256>>>(x, emb, bias_pool, out);
}